// round 2
// baseline (speedup 1.0000x reference)
#include <cuda_runtime.h>
#include <cstdint>

// ---------------- problem constants (from reference) ----------------
#define NPTS_MAX 500000
#define BATCH 2
#define CZ 1
#define CY 400
#define CX 352
#define CL (BATCH * CZ * CY * CX)   // 281600
#define C_H 64
#define C_IN 11

__device__ __constant__ float VXc = 0.2f, VYc = 0.2f, VZc = 4.0f;
__device__ __constant__ float XOFFc = 0.1f;      // VX/2 + X0
__device__ __constant__ float YOFFc = -39.9f;    // VY/2 + Y0
__device__ __constant__ float ZOFFc = -1.0f;     // VZ/2 + Z0

// ---------------- scratch (static device globals; no allocs) ----------------
// pf1 stored as [16 groups][N][4 floats]  -> float4 per (group, point)
__device__ float g_pf1[(size_t)C_H * NPTS_MAX];
__device__ float g_vmax1[(size_t)CL * C_H];
__device__ float g_vsum[(size_t)CL * 3];
__device__ int   g_cnt[CL];

// ---------------- f32x2 helpers (sm_10x packed fp32 FMA) ----------------
__device__ __forceinline__ unsigned long long dup2(float x)
{
    unsigned long long r;
    unsigned int xi = __float_as_uint(x);
    asm("mov.b64 %0, {%1, %1};" : "=l"(r) : "r"(xi));
    return r;
}

__device__ __forceinline__ void ffma2(unsigned long long& acc,
                                      unsigned long long a,
                                      unsigned long long b)
{
    asm("fma.rn.f32x2 %0, %1, %2, %0;" : "+l"(acc) : "l"(a), "l"(b));
}

__device__ __forceinline__ float2 unpack2(unsigned long long v)
{
    unsigned int lo, hi;
    asm("mov.b64 {%0, %1}, %2;" : "=r"(lo), "=r"(hi) : "l"(v));
    return make_float2(__uint_as_float(lo), __uint_as_float(hi));
}

// one k-step: acc[0..31] (pairs of j) += p * W[k][0..63]
__device__ __forceinline__ void fma_row(float p, const longlong2* __restrict__ wrow,
                                        unsigned long long* acc)
{
    unsigned long long pp = dup2(p);
#pragma unroll
    for (int q = 0; q < 16; q++) {
        longlong2 w = wrow[q];                       // LDS.128 (broadcast)
        ffma2(acc[2 * q + 0], pp, (unsigned long long)w.x);
        ffma2(acc[2 * q + 1], pp, (unsigned long long)w.y);
    }
}

// ---------------- K0: zero scratch + output ----------------
__global__ void k_zero(float* __restrict__ out)
{
    const int total = CL * C_H;  // 18,022,400
    for (int i = blockIdx.x * blockDim.x + threadIdx.x; i < total;
         i += gridDim.x * blockDim.x) {
        g_vmax1[i] = 0.0f;
        out[i] = 0.0f;
        if (i < CL * 3) g_vsum[i] = 0.0f;
        if (i < CL)     g_cnt[i] = 0;
    }
}

// ---------------- K1: per-voxel count + xyz sum ----------------
__global__ void k_sums(const float* __restrict__ features,
                       const int* __restrict__ coors, int n)
{
    int i = blockIdx.x * blockDim.x + threadIdx.x;
    if (i >= n) return;
    int b = coors[4 * i + 0];
    int z = coors[4 * i + 1];
    int y = coors[4 * i + 2];
    int x = coors[4 * i + 3];
    int idx = ((b * CZ + z) * CY + y) * CX + x;
    atomicAdd(&g_cnt[idx], 1);
    atomicAdd(&g_vsum[3 * idx + 0], features[4 * i + 0]);
    atomicAdd(&g_vsum[3 * idx + 1], features[4 * i + 1]);
    atomicAdd(&g_vsum[3 * idx + 2], features[4 * i + 2]);
}

// ---------------- K2: feats -> GEMM1 -> relu -> store pf1 + segmax vmax1 ----------------
__global__ void __launch_bounds__(128)
k_pf1(const float* __restrict__ features, const int* __restrict__ coors,
      const float* __restrict__ W1, const float* __restrict__ scale1,
      const float* __restrict__ shift1, int n)
{
    __shared__ alignas(16) float sW1[C_IN][C_H];
    __shared__ float sSc[C_H], sSh[C_H];
    for (int t = threadIdx.x; t < C_IN * C_H; t += blockDim.x)
        sW1[t / C_H][t % C_H] = W1[t];
    if (threadIdx.x < C_H) {
        sSc[threadIdx.x] = scale1[threadIdx.x];
        sSh[threadIdx.x] = shift1[threadIdx.x];
    }
    __syncthreads();

    int i = blockIdx.x * blockDim.x + threadIdx.x;
    if (i >= n) return;

    int b = coors[4 * i + 0];
    int z = coors[4 * i + 1];
    int y = coors[4 * i + 2];
    int x = coors[4 * i + 3];
    int idx = ((b * CZ + z) * CY + y) * CX + x;

    const float4 f = reinterpret_cast<const float4*>(features)[i];

    float inv = 1.0f / fmaxf((float)g_cnt[idx], 1.0f);
    float mx = g_vsum[3 * idx + 0] * inv;
    float my = g_vsum[3 * idx + 1] * inv;
    float mz = g_vsum[3 * idx + 2] * inv;

    float feats[C_IN];
    feats[0] = f.x; feats[1] = f.y; feats[2] = f.z; feats[3] = f.w;
    feats[4] = f.x - mx; feats[5] = f.y - my; feats[6] = f.z - mz;
    feats[7] = f.x - ((float)x * VXc + XOFFc);
    feats[8] = f.y - ((float)y * VYc + YOFFc);
    feats[9] = f.z - ((float)z * VZc + ZOFFc);
    feats[10] = sqrtf(f.x * f.x + f.y * f.y + f.z * f.z);

    unsigned long long acc[32];
#pragma unroll
    for (int q = 0; q < 32; q++) acc[q] = 0ull;

    const longlong2* wll = reinterpret_cast<const longlong2*>(&sW1[0][0]);
#pragma unroll
    for (int k = 0; k < C_IN; k++)
        fma_row(feats[k], wll + k * 16, acc);

    const size_t base = (size_t)idx * C_H;
    float4* pf1_4 = reinterpret_cast<float4*>(g_pf1);

#pragma unroll 1
    for (int g = 0; g < 16; g++) {
        float2 a0 = unpack2(acc[2 * g + 0]);
        float2 a1 = unpack2(acc[2 * g + 1]);
        int j = 4 * g;
        float4 r;
        r.x = fmaxf(fmaf(a0.x, sSc[j + 0], sSh[j + 0]), 0.0f);
        r.y = fmaxf(fmaf(a0.y, sSc[j + 1], sSh[j + 1]), 0.0f);
        r.z = fmaxf(fmaf(a1.x, sSc[j + 2], sSh[j + 2]), 0.0f);
        r.w = fmaxf(fmaf(a1.y, sSc[j + 3], sSh[j + 3]), 0.0f);
        pf1_4[(size_t)g * n + i] = r;
        if (r.x > 0.0f) atomicMax((int*)&g_vmax1[base + j + 0], __float_as_int(r.x));
        if (r.y > 0.0f) atomicMax((int*)&g_vmax1[base + j + 1], __float_as_int(r.y));
        if (r.z > 0.0f) atomicMax((int*)&g_vmax1[base + j + 2], __float_as_int(r.z));
        if (r.w > 0.0f) atomicMax((int*)&g_vmax1[base + j + 3], __float_as_int(r.w));
    }
}

// ---------------- K3: concat(pf1, vmax1[idx]) -> GEMM2 -> relu -> segmax out ----------------
__global__ void __launch_bounds__(128)
k_pf2(const int* __restrict__ coors, const float* __restrict__ W2,
      const float* __restrict__ scale2, const float* __restrict__ shift2,
      float* __restrict__ out, int n)
{
    __shared__ alignas(16) float sW2[2 * C_H][C_H];   // 32KB
    __shared__ float sSc[C_H], sSh[C_H];
    for (int t = threadIdx.x; t < 2 * C_H * C_H; t += blockDim.x)
        sW2[t / C_H][t % C_H] = W2[t];
    if (threadIdx.x < C_H) {
        sSc[threadIdx.x] = scale2[threadIdx.x];
        sSh[threadIdx.x] = shift2[threadIdx.x];
    }
    __syncthreads();

    int i = blockIdx.x * blockDim.x + threadIdx.x;
    if (i >= n) return;

    int b = coors[4 * i + 0];
    int z = coors[4 * i + 1];
    int y = coors[4 * i + 2];
    int x = coors[4 * i + 3];
    int idx = ((b * CZ + z) * CY + y) * CX + x;
    const size_t base = (size_t)idx * C_H;

    unsigned long long acc[32];
#pragma unroll
    for (int q = 0; q < 32; q++) acc[q] = 0ull;

    const longlong2* wll = reinterpret_cast<const longlong2*>(&sW2[0][0]);
    const float4* pf1_4 = reinterpret_cast<const float4*>(g_pf1);
    const float4* vmax_4 = reinterpret_cast<const float4*>(&g_vmax1[base]);

    // first half: pf1 (k = 0..63), float4-grouped scratch layout
#pragma unroll 1
    for (int g = 0; g < 16; g++) {
        float4 p = pf1_4[(size_t)g * n + i];
        const longlong2* w = wll + (4 * g) * 16;
        fma_row(p.x, w + 0 * 16, acc);
        fma_row(p.y, w + 1 * 16, acc);
        fma_row(p.z, w + 2 * 16, acc);
        fma_row(p.w, w + 3 * 16, acc);
    }
    // second half: vmax1[idx] (k = 64..127)
#pragma unroll 1
    for (int g = 0; g < 16; g++) {
        float4 m = vmax_4[g];
        const longlong2* w = wll + (C_H + 4 * g) * 16;
        fma_row(m.x, w + 0 * 16, acc);
        fma_row(m.y, w + 1 * 16, acc);
        fma_row(m.z, w + 2 * 16, acc);
        fma_row(m.w, w + 3 * 16, acc);
    }

#pragma unroll 1
    for (int q = 0; q < 32; q++) {
        float2 a = unpack2(acc[q]);
        int j = 2 * q;
        float v0 = fmaxf(fmaf(a.x, sSc[j + 0], sSh[j + 0]), 0.0f);
        float v1 = fmaxf(fmaf(a.y, sSc[j + 1], sSh[j + 1]), 0.0f);
        if (v0 > 0.0f) atomicMax((int*)&out[base + j + 0], __float_as_int(v0));
        if (v1 > 0.0f) atomicMax((int*)&out[base + j + 1], __float_as_int(v1));
    }
}

// ---------------- launch ----------------
extern "C" void kernel_launch(void* const* d_in, const int* in_sizes, int n_in,
                              void* d_out, int out_size)
{
    const float* features = (const float*)d_in[0];
    const int*   coors    = (const int*)d_in[1];
    const float* W1       = (const float*)d_in[2];
    const float* scale1   = (const float*)d_in[3];
    const float* shift1   = (const float*)d_in[4];
    const float* W2       = (const float*)d_in[5];
    const float* scale2   = (const float*)d_in[6];
    const float* shift2   = (const float*)d_in[7];
    float* out = (float*)d_out;

    int n = in_sizes[0] / 4;   // N points

    k_zero<<<592, 256>>>(out);
    k_sums<<<(n + 255) / 256, 256>>>(features, coors, n);
    k_pf1<<<(n + 127) / 128, 128>>>(features, coors, W1, scale1, shift1, n);
    k_pf2<<<(n + 127) / 128, 128>>>(coors, W2, scale2, shift2, out, n);
}

// round 3
// speedup vs baseline: 1.3501x; 1.3501x over previous
#include <cuda_runtime.h>
#include <cstdint>

// ---------------- problem constants (from reference) ----------------
#define NPTS_MAX 500000
#define BATCH 2
#define CZd 1
#define CYd 400
#define CXd 352
#define CL (BATCH * CZd * CYd * CXd)   // 281600
#define C_H 64
#define C_IN 11

#define TM 128            // points per block in GEMM2
#define AROW 132          // padded A row stride (floats), keeps 16B alignment

__device__ __constant__ float VXc = 0.2f, VYc = 0.2f, VZc = 4.0f;
__device__ __constant__ float XOFFc = 0.1f;
__device__ __constant__ float YOFFc = -39.9f;
__device__ __constant__ float ZOFFc = -1.0f;

// ---------------- scratch (static device globals; no allocs) ----------------
// pf1 stored as [16 groups][N][4 floats] -> float4 per (group, point)
__device__ float g_pf1[(size_t)C_H * NPTS_MAX];
__device__ float g_vmax1[(size_t)CL * C_H];
__device__ float g_vsum[(size_t)CL * 3];
__device__ int   g_cnt[CL];

// ---------------- f32x2 helpers ----------------
__device__ __forceinline__ unsigned long long dup2(float x)
{
    unsigned long long r;
    unsigned int xi = __float_as_uint(x);
    asm("mov.b64 %0, {%1, %1};" : "=l"(r) : "r"(xi));
    return r;
}
__device__ __forceinline__ void ffma2(unsigned long long& acc,
                                      unsigned long long a,
                                      unsigned long long b)
{
    asm("fma.rn.f32x2 %0, %1, %2, %0;" : "+l"(acc) : "l"(a), "l"(b));
}
__device__ __forceinline__ float2 unpack2(unsigned long long v)
{
    unsigned int lo, hi;
    asm("mov.b64 {%0, %1}, %2;" : "=r"(lo), "=r"(hi) : "l"(v));
    return make_float2(__uint_as_float(lo), __uint_as_float(hi));
}

// ---------------- K0: zero scratch + output ----------------
__global__ void k_zero(float* __restrict__ out)
{
    const int total = CL * C_H;  // 18,022,400
    for (int i = blockIdx.x * blockDim.x + threadIdx.x; i < total;
         i += gridDim.x * blockDim.x) {
        g_vmax1[i] = 0.0f;
        out[i] = 0.0f;
        if (i < CL * 3) g_vsum[i] = 0.0f;
        if (i < CL)     g_cnt[i] = 0;
    }
}

// ---------------- K1: per-voxel count + xyz sum ----------------
__global__ void k_sums(const float* __restrict__ features,
                       const int* __restrict__ coors, int n)
{
    int i = blockIdx.x * blockDim.x + threadIdx.x;
    if (i >= n) return;
    int4 c = reinterpret_cast<const int4*>(coors)[i];
    int idx = ((c.x * CZd + c.y) * CYd + c.z) * CXd + c.w;
    float4 f = reinterpret_cast<const float4*>(features)[i];
    atomicAdd(&g_cnt[idx], 1);
    atomicAdd(&g_vsum[3 * idx + 0], f.x);
    atomicAdd(&g_vsum[3 * idx + 1], f.y);
    atomicAdd(&g_vsum[3 * idx + 2], f.z);
}

// ---------------- K2: feats -> GEMM1 -> relu -> store pf1 + segmax vmax1 ----------------
__global__ void __launch_bounds__(128)
k_pf1(const float* __restrict__ features, const int* __restrict__ coors,
      const float* __restrict__ W1, const float* __restrict__ scale1,
      const float* __restrict__ shift1, int n)
{
    __shared__ float sW1[C_IN][C_H];
    __shared__ float sSc[C_H], sSh[C_H];
    for (int t = threadIdx.x; t < C_IN * C_H; t += blockDim.x)
        sW1[t / C_H][t % C_H] = W1[t];
    if (threadIdx.x < C_H) {
        sSc[threadIdx.x] = scale1[threadIdx.x];
        sSh[threadIdx.x] = shift1[threadIdx.x];
    }
    __syncthreads();

    int i = blockIdx.x * blockDim.x + threadIdx.x;
    if (i >= n) return;

    int4 c = reinterpret_cast<const int4*>(coors)[i];
    int idx = ((c.x * CZd + c.y) * CYd + c.z) * CXd + c.w;

    const float4 f = reinterpret_cast<const float4*>(features)[i];

    float inv = 1.0f / fmaxf((float)g_cnt[idx], 1.0f);
    float mx = g_vsum[3 * idx + 0] * inv;
    float my = g_vsum[3 * idx + 1] * inv;
    float mz = g_vsum[3 * idx + 2] * inv;

    float feats[C_IN];
    feats[0] = f.x; feats[1] = f.y; feats[2] = f.z; feats[3] = f.w;
    feats[4] = f.x - mx; feats[5] = f.y - my; feats[6] = f.z - mz;
    feats[7] = f.x - ((float)c.w * VXc + XOFFc);
    feats[8] = f.y - ((float)c.z * VYc + YOFFc);
    feats[9] = f.z - ((float)c.y * VZc + ZOFFc);
    feats[10] = sqrtf(f.x * f.x + f.y * f.y + f.z * f.z);

    float acc[C_H];
#pragma unroll
    for (int j = 0; j < C_H; j++) acc[j] = 0.0f;
#pragma unroll
    for (int k = 0; k < C_IN; k++) {
        float fk = feats[k];
#pragma unroll
        for (int j = 0; j < C_H; j++)
            acc[j] = fmaf(fk, sW1[k][j], acc[j]);
    }

    const size_t base = (size_t)idx * C_H;
    float4* pf1_4 = reinterpret_cast<float4*>(g_pf1);

#pragma unroll 1
    for (int g = 0; g < 16; g++) {
        int j = 4 * g;
        float4 r;
        r.x = fmaxf(fmaf(acc[j + 0], sSc[j + 0], sSh[j + 0]), 0.0f);
        r.y = fmaxf(fmaf(acc[j + 1], sSc[j + 1], sSh[j + 1]), 0.0f);
        r.z = fmaxf(fmaf(acc[j + 2], sSc[j + 2], sSh[j + 2]), 0.0f);
        r.w = fmaxf(fmaf(acc[j + 3], sSc[j + 3], sSh[j + 3]), 0.0f);
        pf1_4[(size_t)g * n + i] = r;
        if (r.x > 0.0f) atomicMax((int*)&g_vmax1[base + j + 0], __float_as_int(r.x));
        if (r.y > 0.0f) atomicMax((int*)&g_vmax1[base + j + 1], __float_as_int(r.y));
        if (r.z > 0.0f) atomicMax((int*)&g_vmax1[base + j + 2], __float_as_int(r.z));
        if (r.w > 0.0f) atomicMax((int*)&g_vmax1[base + j + 3], __float_as_int(r.w));
    }
}

// ---------------- K3: shared-tiled register-blocked GEMM2 + segmax ----------------
// block: 128 threads, tile M=128 points x N=64 cols x K=128 (fully smem resident)
// each thread: 8 points x 8 cols, FFMA2 packed accumulators
__global__ void __launch_bounds__(128)
k_pf2(const int* __restrict__ coors, const float* __restrict__ W2,
      const float* __restrict__ scale2, const float* __restrict__ shift2,
      float* __restrict__ out, int n)
{
    extern __shared__ float sm[];
    float* sA  = sm;                        // [128 k][AROW]  (16896 floats)
    float* sB  = sm + 128 * AROW;           // [128 k][64]    (8192 floats)
    float* sSc = sB + 128 * C_H;            // 64
    float* sSh = sSc + C_H;                 // 64
    int*   sIdx = (int*)(sSh + C_H);        // 128

    const int tid = threadIdx.x;
    const int bstart = blockIdx.x * TM;

    // ---- stage W2 + scale/shift (coalesced) ----
    {
        const float4* w4 = reinterpret_cast<const float4*>(W2);
        float4* b4 = reinterpret_cast<float4*>(sB);
        for (int t = tid; t < 2 * C_H * C_H / 4; t += 128) b4[t] = w4[t];
        if (tid < C_H) { sSc[tid] = scale2[tid]; sSh[tid] = shift2[tid]; }
    }

    // ---- stage idx for the 128 points ----
    const int i = bstart + tid;
    int myIdx = -1;
    if (i < n) {
        int4 c = reinterpret_cast<const int4*>(coors)[i];
        myIdx = ((c.x * CZd + c.y) * CYd + c.z) * CXd + c.w;
    }
    sIdx[tid] = myIdx;

    // ---- stage A first half: pf1 (transpose [g][N][4] -> sA[k][p]) ----
    const float4* pf1_4 = reinterpret_cast<const float4*>(g_pf1);
#pragma unroll 1
    for (int g = 0; g < 16; g++) {
        float4 v = make_float4(0.f, 0.f, 0.f, 0.f);
        if (i < n) v = pf1_4[(size_t)g * n + i];
        int k0 = 4 * g;
        sA[(k0 + 0) * AROW + tid] = v.x;
        sA[(k0 + 1) * AROW + tid] = v.y;
        sA[(k0 + 2) * AROW + tid] = v.z;
        sA[(k0 + 3) * AROW + tid] = v.w;
    }

    // ---- stage A second half: vmax1[idx] gather (L2-resident) ----
    const float4* vmax_4 = reinterpret_cast<const float4*>(g_vmax1);
    const size_t vb = (size_t)(myIdx < 0 ? 0 : myIdx) * 16;
#pragma unroll 1
    for (int g = 0; g < 16; g++) {
        float4 v = make_float4(0.f, 0.f, 0.f, 0.f);
        if (myIdx >= 0) v = vmax_4[vb + g];
        int k0 = C_H + 4 * g;
        sA[(k0 + 0) * AROW + tid] = v.x;
        sA[(k0 + 1) * AROW + tid] = v.y;
        sA[(k0 + 2) * AROW + tid] = v.z;
        sA[(k0 + 3) * AROW + tid] = v.w;
    }
    __syncthreads();

    // ---- mainloop ----
    const int tx = tid & 7;        // N-group: cols tx*8 .. tx*8+7
    const int ty = tid >> 3;       // M-group: points ty*8 .. ty*8+7

    unsigned long long acc[8][4];
#pragma unroll
    for (int mi = 0; mi < 8; mi++)
#pragma unroll
        for (int q = 0; q < 4; q++) acc[mi][q] = 0ull;

    const float* aBase = sA + ty * 8;
    const float* bBase = sB + tx * 8;

#pragma unroll 4
    for (int k = 0; k < 2 * C_H; k++) {
        float4 a0 = *reinterpret_cast<const float4*>(aBase + k * AROW);
        float4 a1 = *reinterpret_cast<const float4*>(aBase + k * AROW + 4);
        ulonglong2 b01 = *reinterpret_cast<const ulonglong2*>(bBase + k * C_H);
        ulonglong2 b23 = *reinterpret_cast<const ulonglong2*>(bBase + k * C_H + 4);
        unsigned long long bb[4] = { b01.x, b01.y, b23.x, b23.y };
        float av[8] = { a0.x, a0.y, a0.z, a0.w, a1.x, a1.y, a1.z, a1.w };
#pragma unroll
        for (int mi = 0; mi < 8; mi++) {
            unsigned long long am = dup2(av[mi]);
#pragma unroll
            for (int q = 0; q < 4; q++) ffma2(acc[mi][q], am, bb[q]);
        }
    }

    // ---- epilogue: affine + relu + atomic segmax ----
    float scv[8], shv[8];
#pragma unroll
    for (int j = 0; j < 8; j++) {
        scv[j] = sSc[tx * 8 + j];
        shv[j] = sSh[tx * 8 + j];
    }

#pragma unroll 1
    for (int mi = 0; mi < 8; mi++) {
        int p = ty * 8 + mi;
        int vidx = sIdx[p];
        if (vidx < 0) continue;
        float* obase = out + (size_t)vidx * C_H + tx * 8;
#pragma unroll
        for (int q = 0; q < 4; q++) {
            float2 a = unpack2(acc[mi][q]);
            float v0 = fmaxf(fmaf(a.x, scv[2 * q + 0], shv[2 * q + 0]), 0.0f);
            float v1 = fmaxf(fmaf(a.y, scv[2 * q + 1], shv[2 * q + 1]), 0.0f);
            if (v0 > 0.0f) atomicMax((int*)&obase[2 * q + 0], __float_as_int(v0));
            if (v1 > 0.0f) atomicMax((int*)&obase[2 * q + 1], __float_as_int(v1));
        }
    }
}

// ---------------- launch ----------------
extern "C" void kernel_launch(void* const* d_in, const int* in_sizes, int n_in,
                              void* d_out, int out_size)
{
    const float* features = (const float*)d_in[0];
    const int*   coors    = (const int*)d_in[1];
    const float* W1       = (const float*)d_in[2];
    const float* scale1   = (const float*)d_in[3];
    const float* shift1   = (const float*)d_in[4];
    const float* W2       = (const float*)d_in[5];
    const float* scale2   = (const float*)d_in[6];
    const float* shift2   = (const float*)d_in[7];
    float* out = (float*)d_out;

    int n = in_sizes[0] / 4;   // N points

    const int smem_pf2 = (128 * AROW + 128 * C_H + 2 * C_H) * 4 + 128 * 4;
    static bool attr_set = false;
    if (!attr_set) {
        cudaFuncSetAttribute(k_pf2, cudaFuncAttributeMaxDynamicSharedMemorySize,
                             smem_pf2);
        attr_set = true;
    }

    k_zero<<<592, 256>>>(out);
    k_sums<<<(n + 255) / 256, 256>>>(features, coors, n);
    k_pf1<<<(n + 127) / 128, 128>>>(features, coors, W1, scale1, shift1, n);
    k_pf2<<<(n + TM - 1) / TM, 128, smem_pf2>>>(coors, W2, scale2, shift2, out, n);
}

// round 4
// speedup vs baseline: 1.4728x; 1.0909x over previous
#include <cuda_runtime.h>
#include <cstdint>

// ---------------- problem constants (from reference) ----------------
#define NPTS_MAX 500000
#define BATCH 2
#define CZd 1
#define CYd 400
#define CXd 352
#define CL (BATCH * CZd * CYd * CXd)   // 281600
#define C_H 64
#define C_IN 11

#define TM 128            // points per block in GEMM2
#define AROW 132          // padded A row stride (floats)

__device__ __constant__ float VXc = 0.2f, VYc = 0.2f, VZc = 4.0f;
__device__ __constant__ float XOFFc = 0.1f;
__device__ __constant__ float YOFFc = -39.9f;
__device__ __constant__ float ZOFFc = -1.0f;

// ---------------- scratch (static device globals; no allocs) ----------------
__device__ float g_pf1[(size_t)C_H * NPTS_MAX];   // [16 g][N][4]
__device__ float g_vmax1[(size_t)CL * C_H];
__device__ float g_vsum[(size_t)CL * 3];
__device__ int   g_cnt[CL];

// ---------------- f32x2 helpers ----------------
__device__ __forceinline__ unsigned long long dup2(float x)
{
    unsigned long long r;
    unsigned int xi = __float_as_uint(x);
    asm("mov.b64 %0, {%1, %1};" : "=l"(r) : "r"(xi));
    return r;
}
__device__ __forceinline__ void ffma2(unsigned long long& acc,
                                      unsigned long long a,
                                      unsigned long long b)
{
    asm("fma.rn.f32x2 %0, %1, %2, %0;" : "+l"(acc) : "l"(a), "l"(b));
}
__device__ __forceinline__ void fadd2(unsigned long long& acc, unsigned long long b)
{
    asm("add.rn.f32x2 %0, %0, %1;" : "+l"(acc) : "l"(b));
}
__device__ __forceinline__ float2 unpack2(unsigned long long v)
{
    unsigned int lo, hi;
    asm("mov.b64 {%0, %1}, %2;" : "=r"(lo), "=r"(hi) : "l"(v));
    return make_float2(__uint_as_float(lo), __uint_as_float(hi));
}

// ---------------- K0: zero scratch + output ----------------
__global__ void k_zero(float* __restrict__ out)
{
    const int total = CL * C_H;
    for (int i = blockIdx.x * blockDim.x + threadIdx.x; i < total;
         i += gridDim.x * blockDim.x) {
        g_vmax1[i] = 0.0f;
        out[i] = 0.0f;
        if (i < CL * 3) g_vsum[i] = 0.0f;
        if (i < CL)     g_cnt[i] = 0;
    }
}

// ---------------- K1: per-voxel count + xyz sum ----------------
__global__ void k_sums(const float* __restrict__ features,
                       const int* __restrict__ coors, int n)
{
    int i = blockIdx.x * blockDim.x + threadIdx.x;
    if (i >= n) return;
    int4 c = reinterpret_cast<const int4*>(coors)[i];
    int idx = ((c.x * CZd + c.y) * CYd + c.z) * CXd + c.w;
    float4 f = reinterpret_cast<const float4*>(features)[i];
    atomicAdd(&g_cnt[idx], 1);
    atomicAdd(&g_vsum[3 * idx + 0], f.x);
    atomicAdd(&g_vsum[3 * idx + 1], f.y);
    atomicAdd(&g_vsum[3 * idx + 2], f.z);
}

// ---------------- K2: feats -> GEMM1 -> relu -> store pf1 + segmax vmax1 ----------------
__global__ void __launch_bounds__(128)
k_pf1(const float* __restrict__ features, const int* __restrict__ coors,
      const float* __restrict__ W1, const float* __restrict__ scale1,
      const float* __restrict__ shift1, int n)
{
    __shared__ float sW1[C_IN][C_H];
    __shared__ float sSc[C_H], sSh[C_H];
    for (int t = threadIdx.x; t < C_IN * C_H; t += blockDim.x)
        sW1[t / C_H][t % C_H] = W1[t];
    if (threadIdx.x < C_H) {
        sSc[threadIdx.x] = scale1[threadIdx.x];
        sSh[threadIdx.x] = shift1[threadIdx.x];
    }
    __syncthreads();

    int i = blockIdx.x * blockDim.x + threadIdx.x;
    if (i >= n) return;

    int4 c = reinterpret_cast<const int4*>(coors)[i];
    int idx = ((c.x * CZd + c.y) * CYd + c.z) * CXd + c.w;

    const float4 f = reinterpret_cast<const float4*>(features)[i];

    float inv = 1.0f / fmaxf((float)g_cnt[idx], 1.0f);
    float mx = g_vsum[3 * idx + 0] * inv;
    float my = g_vsum[3 * idx + 1] * inv;
    float mz = g_vsum[3 * idx + 2] * inv;

    float feats[C_IN];
    feats[0] = f.x; feats[1] = f.y; feats[2] = f.z; feats[3] = f.w;
    feats[4] = f.x - mx; feats[5] = f.y - my; feats[6] = f.z - mz;
    feats[7] = f.x - ((float)c.w * VXc + XOFFc);
    feats[8] = f.y - ((float)c.z * VYc + YOFFc);
    feats[9] = f.z - ((float)c.y * VZc + ZOFFc);
    feats[10] = sqrtf(f.x * f.x + f.y * f.y + f.z * f.z);

    float acc[C_H];
#pragma unroll
    for (int j = 0; j < C_H; j++) acc[j] = 0.0f;
#pragma unroll
    for (int k = 0; k < C_IN; k++) {
        float fk = feats[k];
#pragma unroll
        for (int j = 0; j < C_H; j++)
            acc[j] = fmaf(fk, sW1[k][j], acc[j]);
    }

    const size_t base = (size_t)idx * C_H;
    float4* pf1_4 = reinterpret_cast<float4*>(g_pf1);

#pragma unroll 1
    for (int g = 0; g < 16; g++) {
        int j = 4 * g;
        float4 r;
        r.x = fmaxf(fmaf(acc[j + 0], sSc[j + 0], sSh[j + 0]), 0.0f);
        r.y = fmaxf(fmaf(acc[j + 1], sSc[j + 1], sSh[j + 1]), 0.0f);
        r.z = fmaxf(fmaf(acc[j + 2], sSc[j + 2], sSh[j + 2]), 0.0f);
        r.w = fmaxf(fmaf(acc[j + 3], sSc[j + 3], sSh[j + 3]), 0.0f);
        pf1_4[(size_t)g * n + i] = r;
        if (r.x > 0.0f) atomicMax((int*)&g_vmax1[base + j + 0], __float_as_int(r.x));
        if (r.y > 0.0f) atomicMax((int*)&g_vmax1[base + j + 1], __float_as_int(r.y));
        if (r.z > 0.0f) atomicMax((int*)&g_vmax1[base + j + 2], __float_as_int(r.z));
        if (r.w > 0.0f) atomicMax((int*)&g_vmax1[base + j + 3], __float_as_int(r.w));
    }
}

// ---------------- K3: smem-tiled GEMM2, K-split across 2 thread halves ----------------
// 256 threads. Tile M=128 x N=64 x K=128. Thread-tile 8x8.
// Half kh accumulates k in [kh*64, kh*64+64); halves combined via shared.
__global__ void __launch_bounds__(256, 2)
k_pf2(const int* __restrict__ coors, const float* __restrict__ W2,
      const float* __restrict__ scale2, const float* __restrict__ shift2,
      float* __restrict__ out, int n)
{
    extern __shared__ float sm[];
    float* sA  = sm;                        // [128 k][AROW]
    float* sB  = sm + 128 * AROW;           // [128 k][64]
    float* sSc = sB + 128 * C_H;
    float* sSh = sSc + C_H;
    int*   sIdx = (int*)(sSh + C_H);        // 128

    const int tid = threadIdx.x;
    const int t   = tid & 127;
    const int kh  = tid >> 7;               // 0 or 1
    const int bstart = blockIdx.x * TM;
    const int i = bstart + t;

    // ---- stage W2 + scale/shift (all 256 threads) ----
    {
        const float4* w4 = reinterpret_cast<const float4*>(W2);
        float4* b4 = reinterpret_cast<float4*>(sB);
        for (int v = tid; v < 2 * C_H * C_H / 4; v += 256) b4[v] = w4[v];
        if (tid < C_H) { sSc[tid] = scale2[tid]; sSh[tid] = shift2[tid]; }
    }

    // ---- stage voxel idx (half 0) ----
    if (kh == 0) {
        int myIdx = -1;
        if (i < n) {
            int4 c = reinterpret_cast<const int4*>(coors)[i];
            myIdx = ((c.x * CZd + c.y) * CYd + c.z) * CXd + c.w;
        }
        sIdx[t] = myIdx;
    }
    __syncthreads();

    // ---- stage A: half 0 loads pf1 (k 0..63), half 1 gathers vmax1 (k 64..127) ----
    if (kh == 0) {
        const float4* pf1_4 = reinterpret_cast<const float4*>(g_pf1);
#pragma unroll 1
        for (int g = 0; g < 16; g++) {
            float4 v = make_float4(0.f, 0.f, 0.f, 0.f);
            if (i < n) v = pf1_4[(size_t)g * n + i];
            int k0 = 4 * g;
            sA[(k0 + 0) * AROW + t] = v.x;
            sA[(k0 + 1) * AROW + t] = v.y;
            sA[(k0 + 2) * AROW + t] = v.z;
            sA[(k0 + 3) * AROW + t] = v.w;
        }
    } else {
        const int myIdx = sIdx[t];
        const float4* vmax_4 = reinterpret_cast<const float4*>(g_vmax1);
        const size_t vb = (size_t)(myIdx < 0 ? 0 : myIdx) * 16;
#pragma unroll 1
        for (int g = 0; g < 16; g++) {
            float4 v = make_float4(0.f, 0.f, 0.f, 0.f);
            if (myIdx >= 0) v = vmax_4[vb + g];
            int k0 = C_H + 4 * g;
            sA[(k0 + 0) * AROW + t] = v.x;
            sA[(k0 + 1) * AROW + t] = v.y;
            sA[(k0 + 2) * AROW + t] = v.z;
            sA[(k0 + 3) * AROW + t] = v.w;
        }
    }
    __syncthreads();

    // ---- mainloop over this half's K range ----
    const int tx = t & 7;
    const int ty = t >> 3;

    unsigned long long acc[32];
#pragma unroll
    for (int q = 0; q < 32; q++) acc[q] = 0ull;

    const float* aBase = sA + ty * 8;
    const float* bBase = sB + tx * 8;
    const int kbeg = kh * 64;

#pragma unroll 4
    for (int kk = 0; kk < 64; kk++) {
        int k = kbeg + kk;
        float4 a0 = *reinterpret_cast<const float4*>(aBase + k * AROW);
        float4 a1 = *reinterpret_cast<const float4*>(aBase + k * AROW + 4);
        ulonglong2 b01 = *reinterpret_cast<const ulonglong2*>(bBase + k * C_H);
        ulonglong2 b23 = *reinterpret_cast<const ulonglong2*>(bBase + k * C_H + 4);
        unsigned long long bb[4] = { b01.x, b01.y, b23.x, b23.y };
        float av[8] = { a0.x, a0.y, a0.z, a0.w, a1.x, a1.y, a1.z, a1.w };
#pragma unroll
        for (int mi = 0; mi < 8; mi++) {
            unsigned long long am = dup2(av[mi]);
#pragma unroll
            for (int q = 0; q < 4; q++) ffma2(acc[mi * 4 + q], am, bb[q]);
        }
    }

    // ---- combine halves (reuse sA region as u64 buffer) ----
    __syncthreads();
    unsigned long long* sRed = (unsigned long long*)sA;   // [32][128]
    if (kh == 1) {
#pragma unroll
        for (int q = 0; q < 32; q++) sRed[q * 128 + t] = acc[q];
    }
    __syncthreads();
    if (kh == 1) return;

#pragma unroll
    for (int q = 0; q < 32; q++) fadd2(acc[q], sRed[q * 128 + t]);

    // ---- epilogue: affine + relu + atomic segmax ----
    float scv[8], shv[8];
#pragma unroll
    for (int j = 0; j < 8; j++) {
        scv[j] = sSc[tx * 8 + j];
        shv[j] = sSh[tx * 8 + j];
    }

#pragma unroll 1
    for (int mi = 0; mi < 8; mi++) {
        int p = ty * 8 + mi;
        int vidx = sIdx[p];
        if (vidx < 0) continue;
        float* obase = out + (size_t)vidx * C_H + tx * 8;
#pragma unroll
        for (int q = 0; q < 4; q++) {
            float2 a = unpack2(acc[mi * 4 + q]);
            float v0 = fmaxf(fmaf(a.x, scv[2 * q + 0], shv[2 * q + 0]), 0.0f);
            float v1 = fmaxf(fmaf(a.y, scv[2 * q + 1], shv[2 * q + 1]), 0.0f);
            if (v0 > 0.0f) atomicMax((int*)&obase[2 * q + 0], __float_as_int(v0));
            if (v1 > 0.0f) atomicMax((int*)&obase[2 * q + 1], __float_as_int(v1));
        }
    }
}

// ---------------- launch ----------------
extern "C" void kernel_launch(void* const* d_in, const int* in_sizes, int n_in,
                              void* d_out, int out_size)
{
    const float* features = (const float*)d_in[0];
    const int*   coors    = (const int*)d_in[1];
    const float* W1       = (const float*)d_in[2];
    const float* scale1   = (const float*)d_in[3];
    const float* shift1   = (const float*)d_in[4];
    const float* W2       = (const float*)d_in[5];
    const float* scale2   = (const float*)d_in[6];
    const float* shift2   = (const float*)d_in[7];
    float* out = (float*)d_out;

    int n = in_sizes[0] / 4;   // N points

    const int smem_pf2 = (128 * AROW + 128 * C_H + 2 * C_H) * 4 + 128 * 4;
    static bool attr_set = false;
    if (!attr_set) {
        cudaFuncSetAttribute(k_pf2, cudaFuncAttributeMaxDynamicSharedMemorySize,
                             smem_pf2);
        attr_set = true;
    }

    k_zero<<<592, 256>>>(out);
    k_sums<<<(n + 255) / 256, 256>>>(features, coors, n);
    k_pf1<<<(n + 127) / 128, 128>>>(features, coors, W1, scale1, shift1, n);
    k_pf2<<<(n + TM - 1) / TM, 256, smem_pf2>>>(coors, W2, scale2, shift2, out, n);
}